// round 12
// baseline (speedup 1.0000x reference)
#include <cuda_runtime.h>

#define BB 64
#define TT 4096
#define HH 128
#define GG 384    /* 3H */
#define NPAIR 32  /* producer/consumer CTAs each handle 2 batches */
#define NWORK 84  /* GEMM workers; 32+32+84 = 148 = full wave-1 residency */

// Scratch (allocation-free rule: __device__ globals)
__device__ float g_y0[(size_t)BB * TT * HH];    // layer-0 outputs [b][t][k]  128 MiB
__device__ float g_xg1[(size_t)BB * TT * GG];   // layer-1 ih gates [b][t][g] 402 MiB
__device__ float g_y1[(size_t)BB * TT * HH];    // layer-1 outputs [b][t][k]  128 MiB
__device__ int   g_flagA[BB * 32];              // y0 chunk ready  (producer -> worker)
__device__ int   g_flagB[BB * 32];              // xg1 chunk ready (worker -> consumer)

typedef unsigned long long ull;

static __device__ __forceinline__ ull pk(float a, float b) {
    ull r; asm("mov.b64 %0, {%1, %2};" : "=l"(r) : "f"(a), "f"(b)); return r;
}
static __device__ __forceinline__ void upk(ull v, float& a, float& b) {
    asm("mov.b64 {%0, %1}, %2;" : "=f"(a), "=f"(b) : "l"(v));
}
// Packed fp32x2 FMA / ADD (Blackwell): 2 ops per issue slot
static __device__ __forceinline__ void ffma2(ull& acc, ull a, ull b) {
    asm("fma.rn.f32x2 %0, %1, %2, %0;" : "+l"(acc) : "l"(a), "l"(b));
}
static __device__ __forceinline__ ull add2(ull a, ull b) {
    ull r; asm("add.rn.f32x2 %0, %1, %2;" : "=l"(r) : "l"(a), "l"(b)); return r;
}
static __device__ __forceinline__ float red2(ull a, ull b) {
    ull s = add2(a, b); float x0, x1; upk(s, x0, x1); return x0 + x1;
}
static __device__ __forceinline__ float tanha(float x) {     // MUFU tanh
    float y; asm("tanh.approx.f32 %0, %1;" : "=f"(y) : "f"(x)); return y;
}
static __device__ __forceinline__ float sigfast(float x) {   // sigmoid via MUFU tanh
    return fmaf(0.5f, tanha(0.5f * x), 0.5f);
}
static __device__ __forceinline__ int ldacq(const int* p) {
    int v; asm volatile("ld.acquire.gpu.global.b32 %0, [%1];" : "=r"(v) : "l"(p) : "memory");
    return v;
}
static __device__ __forceinline__ void strel(int* p, int v) {
    asm volatile("st.release.gpu.global.b32 [%0], %1;" :: "l"(p), "r"(v) : "memory");
}
static __device__ __forceinline__ void stplain(int* p, int v) {
    asm volatile("st.global.b32 [%0], %1;" :: "l"(p), "r"(v) : "memory");
}

// Load one full 128-float weight row into 64 packed pairs (worker path).
static __device__ __forceinline__ void loadw(ull* w, const float* __restrict__ row) {
    const float4* r4 = (const float4*)row;
#pragma unroll
    for (int i = 0; i < 32; i++) {
        float4 v = r4[i];
        w[2 * i]     = pk(v.x, v.y);
        w[2 * i + 1] = pk(v.z, v.w);
    }
}
// Load a 32-float quarter-row into 16 packed pairs (recurrence path).
static __device__ __forceinline__ void loadw32(ull* w, const float* __restrict__ row) {
    const float4* r4 = (const float4*)row;
#pragma unroll
    for (int i = 0; i < 8; i++) {
        float4 v = r4[i];
        w[2 * i]     = pk(v.x, v.y);
        w[2 * i + 1] = pk(v.z, v.w);
    }
}

// Full dot (worker path): 32 LDS.128 + 64 FFMA2, 4 chains.
static __device__ __forceinline__ float dot128(const ull* w, const float* hsm) {
    const ulonglong2* h2 = (const ulonglong2*)hsm;
    ull a0 = 0, a1 = 0, a2 = 0, a3 = 0;
#pragma unroll
    for (int k = 0; k < 16; k++) {
        ulonglong2 p = h2[2 * k];
        ulonglong2 q = h2[2 * k + 1];
        ffma2(a0, w[4 * k + 0], p.x);
        ffma2(a1, w[4 * k + 1], p.y);
        ffma2(a2, w[4 * k + 2], q.x);
        ffma2(a3, w[4 * k + 3], q.y);
    }
    return red2(add2(a0, a1), add2(a2, a3));
}

// Recurrence dot: this thread's QUARTER of h (8 LDS.128) feeding FOUR adjacent
// rows' quarter-dots (4 independent chains, 16 FFMA2 each).
static __device__ __forceinline__ void dot4q(const ull w[4][16], const float* hsm,
                                             int qoff8, float* v) {
    const ulonglong2* h2 = (const ulonglong2*)hsm + qoff8;   // quarter q: +8q
    ull a0 = 0, a1 = 0, a2 = 0, a3 = 0;
#pragma unroll
    for (int k = 0; k < 8; k++) {
        ulonglong2 q = h2[k];
        ffma2(a0, w[0][2 * k], q.x); ffma2(a0, w[0][2 * k + 1], q.y);
        ffma2(a1, w[1][2 * k], q.x); ffma2(a1, w[1][2 * k + 1], q.y);
        ffma2(a2, w[2][2 * k], q.x); ffma2(a2, w[2][2 * k + 1], q.y);
        ffma2(a3, w[3][2 * k], q.x); ffma2(a3, w[3][2 * k + 1], q.y);
    }
    float x0, x1;
    upk(a0, x0, x1); v[0] = x0 + x1;
    upk(a1, x0, x1); v[1] = x0 + x1;
    upk(a2, x0, x1); v[2] = x0 + x1;
    upk(a3, x0, x1); v[3] = x0 + x1;
}

// Combine 4 quarter-dots across lanes {j, j+8, j+16, j+24} (2 butterfly
// rounds). Lane (q1,q0) ends with the FULL dot of row base+4j+2*q1+q0.
static __device__ __forceinline__ float combine4(const float* v, int q0, int q1) {
    float s_lo = q0 ? v[0] : v[1];
    float k_lo = q0 ? v[1] : v[0];
    float s_hi = q0 ? v[2] : v[3];
    float k_hi = q0 ? v[3] : v[2];
    float u0 = k_lo + __shfl_xor_sync(0xffffffffu, s_lo, 8);
    float u1 = k_hi + __shfl_xor_sync(0xffffffffu, s_hi, 8);
    float s2 = q1 ? u0 : u1;
    float k2 = q1 ? u1 : u0;
    return k2 + __shfl_xor_sync(0xffffffffu, s2, 16);
}

// ===== Wavefront mega-kernel with 2-batch-interleaved recurrences =====
//   CTA 0..31  : layer-0 producer for batches (2k, 2k+1)
//   CTA 32..63 : layer-1 consumer for batches (2k, 2k+1), chunk-gated on flagB
//   CTA 64..147: 84 GEMM workers (flagA -> xg1 chunk -> flagB)
// Both batches of a pair share the SAME weight registers. Per-batch state is
// addressed via ONE base pointer + compile-time immediate offsets (TT, TT*HH,
// TT*GG, 32) to stay under the 168-reg cap — no spills in the hot loop.
// Consumer x comes through a 4-slot SMEM ring filled 2 steps ahead with
// coalesced LDG.128 (visibility via the two intervening block barriers).
__global__ void __launch_bounds__(384, 1)
k_main(const float* __restrict__ data, const float* __restrict__ hidden,
       const float* __restrict__ w_ih0, const float* __restrict__ w_hh0,
       const float* __restrict__ b_ih0, const float* __restrict__ b_hh0,
       const float* __restrict__ w_ih1, const float* __restrict__ w_hh1,
       const float* __restrict__ b_ih1, const float* __restrict__ b_hh1,
       float* __restrict__ hT) {
    __shared__ __align__(16) float hsm[2][2][HH];    // [buf][batch][unit]
    __shared__ __align__(8) float2 s_rz[2][HH];      // [batch][unit]
    __shared__ __align__(16) float xs[4][2][GG];     // consumer x ring [slot][batch][gate]
    __shared__ __align__(16) float ybuf[8 * HH];

    const int tid = threadIdx.x;

    if (blockIdx.x >= 2 * NPAIR) {
        // ---------------- WORKER: xg1 = y0 @ w_ih1.T + b_ih1 ----------------
        const int wk = blockIdx.x - 2 * NPAIR;
        ull w[64];
        loadw(w, w_ih1 + tid * HH);
        const float bi = b_ih1[tid];

        for (int task = wk; task < BB * 32; task += NWORK) {
            const int c = task >> 6, b = task & 63;   // chunk-major = production order
            if (tid == 0) {
                const int* f = g_flagA + b * 32 + c;
                while (ldacq(f) == 0) __nanosleep(64);
            }
            __syncthreads();
            const float* y0 = g_y0 + ((size_t)b * TT + (size_t)c * 128) * HH;
            float* xo = g_xg1 + ((size_t)b * TT + (size_t)c * 128) * GG;
            for (int tt = 0; tt < 128; tt += 8) {
                if (tid < 256) ((float4*)ybuf)[tid] = ((const float4*)(y0 + (size_t)tt * HH))[tid];
                __syncthreads();
#pragma unroll
                for (int r = 0; r < 8; r++) {
                    float acc = dot128(w, ybuf + r * HH);
                    xo[(size_t)(tt + r) * GG + tid] = acc + bi;
                }
                __syncthreads();
            }
            if (tid == 0) {
                stplain(g_flagA + b * 32 + c, 0);     // self-reset for next replay
                strel(g_flagB + b * 32 + c, 1);
            }
        }
        return;
    }

    const int warp = tid >> 5, lane = tid & 31;
    const int role = warp >> 2;            // 0=r, 1=z, 2=n
    const int blk  = warp & 3;
    const int q    = lane >> 3;
    const int q0   = q & 1, q1 = q >> 1;
    const int j    = lane & 7;
    const int base = (role << 7) | (blk << 5) | (j << 2);
    const int unit = (blk << 5) | (j << 2) | (q1 << 1) | q0;
    const int grow = (role << 7) | unit;
    const int qoff8 = q << 3;

    if (blockIdx.x < NPAIR) {
        // ======== PRODUCER: layer-0 recurrence, batches b0=2k, b0+1 ========
        const int b0 = 2 * blockIdx.x;
        ull w[4][16];
#pragma unroll
        for (int r = 0; r < 4; r++)
            loadw32(w[r], w_hh0 + (size_t)(base + r) * HH + q * 32);
        const float wi = w_ih0[grow], bi = b_ih0[grow], bh = b_hh0[grow];

        float h0 = hidden[b0 * HH + unit];
        float h1 = hidden[b0 * HH + HH + unit];
        if (role == 2) { hsm[0][0][unit] = h0; hsm[0][1][unit] = h1; }
        __syncthreads();

        const float* xg = data + b0 * TT;            // batch1 at +TT (imm)
        float* yp = g_y0 + (size_t)b0 * TT * HH + unit;  // batch1 at +TT*HH (imm)
        int* fl = g_flagA + b0 * 32;                 // batch1 at +32 (imm)

        int cur = 0;
        float x0 = xg[0], x1 = xg[TT];
        for (int t = 0; t < TT; t++) {
            float xn0 = (t + 1 < TT) ? xg[t + 1] : 0.f;
            float xn1 = (t + 1 < TT) ? xg[t + 1 + TT] : 0.f;
            float v0[4], v1[4];
            dot4q(w, hsm[cur][0], qoff8, v0);
            dot4q(w, hsm[cur][1], qoff8, v1);
            float acc0 = combine4(v0, q0, q1) + bh;
            float acc1 = combine4(v1, q0, q1) + bh;
            float xi0 = fmaf(x0, wi, bi);
            float xi1 = fmaf(x1, wi, bi);
            if (role == 0) {
                s_rz[0][unit].x = sigfast(acc0 + xi0);
                s_rz[1][unit].x = sigfast(acc1 + xi1);
            } else if (role == 1) {
                s_rz[0][unit].y = sigfast(acc0 + xi0);
                s_rz[1][unit].y = sigfast(acc1 + xi1);
            }
            asm volatile("bar.sync %0, 96;" :: "r"(blk + 1) : "memory");
            if (role == 2) {
                float2 rz0 = s_rz[0][unit];
                float2 rz1 = s_rz[1][unit];
                float n0 = tanha(fmaf(rz0.x, acc0, xi0));
                float n1 = tanha(fmaf(rz1.x, acc1, xi1));
                h0 = fmaf(rz0.y, h0 - n0, n0);
                h1 = fmaf(rz1.y, h1 - n1, n1);
                hsm[cur ^ 1][0][unit] = h0;
                hsm[cur ^ 1][1][unit] = h1;
                yp[0] = h0;
                yp[TT * HH] = h1;     // immediate offset, no extra pointer reg
            }
            __syncthreads();
            if (((t & 127) == 127) && tid == 0) {   // publish both chunks
                strel(fl + (t >> 7), 1);
                strel(fl + 32 + (t >> 7), 1);
            }
            x0 = xn0; x1 = xn1;
            if (role == 2) yp += HH;
            cur ^= 1;
        }
        if (role == 2) {
            hT[b0 * HH + unit] = h0;
            hT[b0 * HH + HH + unit] = h1;
        }
    } else {
        // ======== CONSUMER: layer-1 recurrence, batches b0=2k, b0+1 ========
        const int b0 = 2 * (blockIdx.x - NPAIR);
        ull w[4][16];
#pragma unroll
        for (int r = 0; r < 4; r++)
            loadw32(w[r], w_hh1 + (size_t)(base + r) * HH + q * 32);
        const float bh = b_hh1[grow];

        float h0 = hidden[(BB + b0) * HH + unit];
        float h1 = hidden[(BB + b0) * HH + HH + unit];
        if (role == 2) { hsm[0][0][unit] = h0; hsm[0][1][unit] = h1; }

        // x ring prefetchers: warps 0-5; each thread owns one float4 of one batch
        const bool pref = (tid < 192);
        const int pbb = (tid >= 96) ? 1 : 0;
        const int pidx = (tid - 96 * pbb) << 2;          // float index 0..380
        const float* xsrc = g_xg1 + (size_t)b0 * TT * GG + (size_t)pbb * TT * GG + pidx;

        float* yp = g_y1 + (size_t)b0 * TT * HH + unit;  // batch1 at +TT*HH (imm)
        int* fl = g_flagB + b0 * 32;                     // batch1 at +32 (imm)

        int cur = 0;
        for (int c = 0; c < 32; c++) {
            if (tid == 0) {
                while (ldacq(fl + c) == 0) __nanosleep(64);
                while (ldacq(fl + c + 32) == 0) __nanosleep(64);
            }
            __syncthreads();     // flag visible; also orders initial hsm writes
            int xoff = c * 128 * GG;                     // row offset (floats)
            if (pref) {          // warm ring slots 0,1 with rows t0, t0+1
                float4 a = *(const float4*)(xsrc + xoff);
                float4 bv = *(const float4*)(xsrc + xoff + GG);
                *(float4*)&xs[0][pbb][pidx] = a;
                *(float4*)&xs[1][pbb][pidx] = bv;
            }
            __syncthreads();
            for (int tt = 0; tt < 128; tt++) {
                const int slot = tt & 3;
                if (pref && tt < 126) {                  // prefetch row t+2
                    float4 a = *(const float4*)(xsrc + xoff + 2 * GG);
                    *(float4*)&xs[(tt + 2) & 3][pbb][pidx] = a;
                }
                float x0 = xs[slot][0][grow];            // conflict-free LDS
                float x1 = xs[slot][1][grow];
                float v0[4], v1[4];
                dot4q(w, hsm[cur][0], qoff8, v0);
                dot4q(w, hsm[cur][1], qoff8, v1);
                float acc0 = combine4(v0, q0, q1) + bh;
                float acc1 = combine4(v1, q0, q1) + bh;
                if (role == 0) {
                    s_rz[0][unit].x = sigfast(acc0 + x0);
                    s_rz[1][unit].x = sigfast(acc1 + x1);
                } else if (role == 1) {
                    s_rz[0][unit].y = sigfast(acc0 + x0);
                    s_rz[1][unit].y = sigfast(acc1 + x1);
                }
                asm volatile("bar.sync %0, 96;" :: "r"(blk + 1) : "memory");
                if (role == 2) {
                    float2 rz0 = s_rz[0][unit];
                    float2 rz1 = s_rz[1][unit];
                    float n0 = tanha(fmaf(rz0.x, acc0, x0));
                    float n1 = tanha(fmaf(rz1.x, acc1, x1));
                    h0 = fmaf(rz0.y, h0 - n0, n0);
                    h1 = fmaf(rz1.y, h1 - n1, n1);
                    hsm[cur ^ 1][0][unit] = h0;
                    hsm[cur ^ 1][1][unit] = h1;
                    yp[0] = h0;
                    yp[TT * HH] = h1;
                }
                __syncthreads();
                xoff += GG;
                if (role == 2) yp += HH;
                cur ^= 1;
            }
            if (tid == 0) {                     // self-reset for next replay
                stplain(fl + c, 0);
                stplain(fl + c + 32, 0);
            }
        }
        if (role == 2) {
            hT[(BB + b0) * HH + unit] = h0;
            hT[(BB + b0) * HH + HH + unit] = h1;
        }
    }
}

// ---------- Tail: out[b,t] = relu(y1[b,t,:]) . fc_w + fc_b  (memory-bound) ----------
__global__ void __launch_bounds__(256)
k_fc(const float* __restrict__ fc_w, const float* __restrict__ fc_b,
     float* __restrict__ out) {
    const int row = blockIdx.x * 8 + (threadIdx.x >> 5);   // row = b*TT + t
    const int lane = threadIdx.x & 31;
    float4 yv = ((const float4*)(g_y1 + (size_t)row * HH))[lane];
    float4 wv = ((const float4*)fc_w)[lane];
    float p = fmaxf(yv.x, 0.f) * wv.x + fmaxf(yv.y, 0.f) * wv.y
            + fmaxf(yv.z, 0.f) * wv.z + fmaxf(yv.w, 0.f) * wv.w;
    p += __shfl_xor_sync(0xffffffffu, p, 16);
    p += __shfl_xor_sync(0xffffffffu, p, 8);
    p += __shfl_xor_sync(0xffffffffu, p, 4);
    p += __shfl_xor_sync(0xffffffffu, p, 2);
    p += __shfl_xor_sync(0xffffffffu, p, 1);
    if (lane == 0) out[row] = p + fc_b[0];
}

extern "C" void kernel_launch(void* const* d_in, const int* in_sizes, int n_in,
                              void* d_out, int out_size) {
    const float* data   = (const float*)d_in[0];
    const float* hidden = (const float*)d_in[1];
    const float* w_ih0  = (const float*)d_in[2];
    const float* w_hh0  = (const float*)d_in[3];
    const float* b_ih0  = (const float*)d_in[4];
    const float* b_hh0  = (const float*)d_in[5];
    const float* w_ih1  = (const float*)d_in[6];
    const float* w_hh1  = (const float*)d_in[7];
    const float* b_ih1  = (const float*)d_in[8];
    const float* b_hh1  = (const float*)d_in[9];
    const float* fc_w   = (const float*)d_in[10];
    const float* fc_b   = (const float*)d_in[11];

    float* out = (float*)d_out;
    float* hT  = out + (size_t)BB * TT;   // [2,B,H] final hidden

    k_main<<<2 * NPAIR + NWORK, 384>>>(data, hidden, w_ih0, w_hh0, b_ih0, b_hh0,
                                       w_ih1, w_hh1, b_ih1, b_hh1, hT);
    k_fc<<<BB * TT / 8, 256>>>(fc_w, fc_b, out);
}

// round 13
// speedup vs baseline: 1.0122x; 1.0122x over previous
#include <cuda_runtime.h>

#define BB 64
#define TT 4096
#define HH 128
#define GG 384    /* 3H */
#define NPAIR 32  /* producer/consumer CTAs each handle 2 batches */
#define NWORK 84  /* GEMM workers; 32+32+84 = 148 = full wave-1 residency */

// Scratch (allocation-free rule: __device__ globals)
__device__ float g_y0[(size_t)BB * TT * HH];    // layer-0 outputs [b][t][k]  128 MiB
__device__ float g_xg1[(size_t)BB * TT * GG];   // layer-1 ih gates [b][t][g] 402 MiB
__device__ float g_y1[(size_t)BB * TT * HH];    // layer-1 outputs [b][t][k]  128 MiB
__device__ int   g_flagA[BB * 32];              // y0 chunk ready  (producer -> worker)
__device__ int   g_flagB[BB * 32];              // xg1 chunk ready (worker -> consumer)

typedef unsigned long long ull;

static __device__ __forceinline__ ull pk(float a, float b) {
    ull r; asm("mov.b64 %0, {%1, %2};" : "=l"(r) : "f"(a), "f"(b)); return r;
}
static __device__ __forceinline__ void upk(ull v, float& a, float& b) {
    asm("mov.b64 {%0, %1}, %2;" : "=f"(a), "=f"(b) : "l"(v));
}
// Packed fp32x2 FMA / ADD (Blackwell): 2 ops per issue slot
static __device__ __forceinline__ void ffma2(ull& acc, ull a, ull b) {
    asm("fma.rn.f32x2 %0, %1, %2, %0;" : "+l"(acc) : "l"(a), "l"(b));
}
static __device__ __forceinline__ ull add2(ull a, ull b) {
    ull r; asm("add.rn.f32x2 %0, %1, %2;" : "=l"(r) : "l"(a), "l"(b)); return r;
}
static __device__ __forceinline__ float red2(ull a, ull b) {
    ull s = add2(a, b); float x0, x1; upk(s, x0, x1); return x0 + x1;
}
static __device__ __forceinline__ float tanha(float x) {     // MUFU tanh
    float y; asm("tanh.approx.f32 %0, %1;" : "=f"(y) : "f"(x)); return y;
}
static __device__ __forceinline__ float sigfast(float x) {   // sigmoid via MUFU tanh
    return fmaf(0.5f, tanha(0.5f * x), 0.5f);
}
static __device__ __forceinline__ int ldacq(const int* p) {
    int v; asm volatile("ld.acquire.gpu.global.b32 %0, [%1];" : "=r"(v) : "l"(p) : "memory");
    return v;
}
static __device__ __forceinline__ void strel(int* p, int v) {
    asm volatile("st.release.gpu.global.b32 [%0], %1;" :: "l"(p), "r"(v) : "memory");
}
static __device__ __forceinline__ void stplain(int* p, int v) {
    asm volatile("st.global.b32 [%0], %1;" :: "l"(p), "r"(v) : "memory");
}

// Load one full 128-float weight row into 64 packed pairs (worker path).
static __device__ __forceinline__ void loadw(ull* w, const float* __restrict__ row) {
    const float4* r4 = (const float4*)row;
#pragma unroll
    for (int i = 0; i < 32; i++) {
        float4 v = r4[i];
        w[2 * i]     = pk(v.x, v.y);
        w[2 * i + 1] = pk(v.z, v.w);
    }
}
// Load a 32-float quarter-row into 16 packed pairs (recurrence path).
static __device__ __forceinline__ void loadw32(ull* w, const float* __restrict__ row) {
    const float4* r4 = (const float4*)row;
#pragma unroll
    for (int i = 0; i < 8; i++) {
        float4 v = r4[i];
        w[2 * i]     = pk(v.x, v.y);
        w[2 * i + 1] = pk(v.z, v.w);
    }
}

// Full dot (worker path): 32 LDS.128 + 64 FFMA2, 4 chains.
static __device__ __forceinline__ float dot128(const ull* w, const float* hsm) {
    const ulonglong2* h2 = (const ulonglong2*)hsm;
    ull a0 = 0, a1 = 0, a2 = 0, a3 = 0;
#pragma unroll
    for (int k = 0; k < 16; k++) {
        ulonglong2 p = h2[2 * k];
        ulonglong2 q = h2[2 * k + 1];
        ffma2(a0, w[4 * k + 0], p.x);
        ffma2(a1, w[4 * k + 1], p.y);
        ffma2(a2, w[4 * k + 2], q.x);
        ffma2(a3, w[4 * k + 3], q.y);
    }
    return red2(add2(a0, a1), add2(a2, a3));
}

// Recurrence dot: this thread's QUARTER of h (8 LDS.128) feeding FOUR adjacent
// rows' quarter-dots (4 independent chains, 16 FFMA2 each).
static __device__ __forceinline__ void dot4q(const ull w[4][16], const float* hsm,
                                             int qoff8, float* v) {
    const ulonglong2* h2 = (const ulonglong2*)hsm + qoff8;   // quarter q: +8q
    ull a0 = 0, a1 = 0, a2 = 0, a3 = 0;
#pragma unroll
    for (int k = 0; k < 8; k++) {
        ulonglong2 q = h2[k];
        ffma2(a0, w[0][2 * k], q.x); ffma2(a0, w[0][2 * k + 1], q.y);
        ffma2(a1, w[1][2 * k], q.x); ffma2(a1, w[1][2 * k + 1], q.y);
        ffma2(a2, w[2][2 * k], q.x); ffma2(a2, w[2][2 * k + 1], q.y);
        ffma2(a3, w[3][2 * k], q.x); ffma2(a3, w[3][2 * k + 1], q.y);
    }
    float x0, x1;
    upk(a0, x0, x1); v[0] = x0 + x1;
    upk(a1, x0, x1); v[1] = x0 + x1;
    upk(a2, x0, x1); v[2] = x0 + x1;
    upk(a3, x0, x1); v[3] = x0 + x1;
}

// Combine 4 quarter-dots across lanes {j, j+8, j+16, j+24} (2 butterfly
// rounds). Lane (q1,q0) ends with the FULL dot of row base+4j+2*q1+q0.
static __device__ __forceinline__ float combine4(const float* v, int q0, int q1) {
    float s_lo = q0 ? v[0] : v[1];
    float k_lo = q0 ? v[1] : v[0];
    float s_hi = q0 ? v[2] : v[3];
    float k_hi = q0 ? v[3] : v[2];
    float u0 = k_lo + __shfl_xor_sync(0xffffffffu, s_lo, 8);
    float u1 = k_hi + __shfl_xor_sync(0xffffffffu, s_hi, 8);
    float s2 = q1 ? u0 : u1;
    float k2 = q1 ? u1 : u0;
    return k2 + __shfl_xor_sync(0xffffffffu, s2, 16);
}

// ===== Wavefront mega-kernel with 2-batch-interleaved recurrences =====
//   CTA 0..31  : layer-0 producer for batches (2k, 2k+1)
//   CTA 32..63 : layer-1 consumer for batches (2k, 2k+1), chunk-gated on flagB
//   CTA 64..147: 84 GEMM workers (flagA -> xg1 chunk -> flagB)
// Tail redistribution: pre-bar role0 keeps sig(r,b0) & ships sig(r,b1);
// role1 keeps sig(z,b1) & ships sig(z,b0); role2 ships (acc_n, xi_n) pairs.
// Post-bar role0 updates h(b0), role1 updates h(b1) in parallel; role2 is
// free and issues the global y stores LAG-1 at the top of the next step
// (ordered by the intervening __syncthreads). Chunk flags publish one step
// late accordingly. Flags reset by their unique consumer => replay-safe.
__global__ void __launch_bounds__(384, 1)
k_main(const float* __restrict__ data, const float* __restrict__ hidden,
       const float* __restrict__ w_ih0, const float* __restrict__ w_hh0,
       const float* __restrict__ b_ih0, const float* __restrict__ b_hh0,
       const float* __restrict__ w_ih1, const float* __restrict__ w_hh1,
       const float* __restrict__ b_ih1, const float* __restrict__ b_hh1,
       float* __restrict__ hT) {
    __shared__ __align__(16) float hsm[2][2][HH];    // [buf][batch][unit]
    __shared__ float s_g[2][HH];                     // [0]=sig_z(b0), [1]=sig_r(b1)
    __shared__ __align__(8) float2 s_n[2][HH];       // (acc_n, xi_n) per batch
    __shared__ __align__(16) float ybuf[8 * HH];

    const int tid = threadIdx.x;

    if (blockIdx.x >= 2 * NPAIR) {
        // ---------------- WORKER: xg1 = y0 @ w_ih1.T + b_ih1 ----------------
        const int wk = blockIdx.x - 2 * NPAIR;
        ull w[64];
        loadw(w, w_ih1 + tid * HH);
        const float bi = b_ih1[tid];

        for (int task = wk; task < BB * 32; task += NWORK) {
            const int c = task >> 6, b = task & 63;   // chunk-major = production order
            if (tid == 0) {
                const int* f = g_flagA + b * 32 + c;
                while (ldacq(f) == 0) __nanosleep(64);
            }
            __syncthreads();
            const float* y0 = g_y0 + ((size_t)b * TT + (size_t)c * 128) * HH;
            float* xo = g_xg1 + ((size_t)b * TT + (size_t)c * 128) * GG;
            for (int tt = 0; tt < 128; tt += 8) {
                if (tid < 256) ((float4*)ybuf)[tid] = ((const float4*)(y0 + (size_t)tt * HH))[tid];
                __syncthreads();
#pragma unroll
                for (int r = 0; r < 8; r++) {
                    float acc = dot128(w, ybuf + r * HH);
                    xo[(size_t)(tt + r) * GG + tid] = acc + bi;
                }
                __syncthreads();
            }
            if (tid == 0) {
                stplain(g_flagA + b * 32 + c, 0);     // self-reset for next replay
                strel(g_flagB + b * 32 + c, 1);
            }
        }
        return;
    }

    const int warp = tid >> 5, lane = tid & 31;
    const int role = warp >> 2;            // 0=r, 1=z, 2=n
    const int blk  = warp & 3;
    const int q    = lane >> 3;
    const int q0   = q & 1, q1 = q >> 1;
    const int j    = lane & 7;
    const int base = (role << 7) | (blk << 5) | (j << 2);
    const int unit = (blk << 5) | (j << 2) | (q1 << 1) | q0;
    const int grow = (role << 7) | unit;
    const int qoff8 = q << 3;

    if (blockIdx.x < NPAIR) {
        // ======== PRODUCER: layer-0 recurrence, batches b0=2k, b0+1 ========
        const int b0 = 2 * blockIdx.x;
        ull w[4][16];
#pragma unroll
        for (int r = 0; r < 4; r++)
            loadw32(w[r], w_hh0 + (size_t)(base + r) * HH + q * 32);
        const float wi = w_ih0[grow], bi = b_ih0[grow], bh = b_hh0[grow];

        // role0 owns h(b0), role1 owns h(b0+1)
        float hmine = hidden[(size_t)(b0 + (role == 1 ? 1 : 0)) * HH + unit];
        if (role == 0) hsm[0][0][unit] = hmine;
        else if (role == 1) hsm[0][1][unit] = hmine;
        __syncthreads();

        const float* xg = data + (size_t)b0 * TT;
        float* yp = g_y0 + (size_t)b0 * TT * HH + unit;  // role2's lag-1 store ptr
        int* fl = g_flagA + b0 * 32;

        int cur = 0;
        float x0 = xg[0], x1 = xg[TT];
        for (int t = 0; t < TT; t++) {
            if (role == 2 && t > 0) {            // lag-1 y store, off critical path
                yp[0] = hsm[cur][0][unit];
                yp[(size_t)TT * HH] = hsm[cur][1][unit];
                yp += HH;
            }
            float xn0 = (t + 1 < TT) ? xg[t + 1] : 0.f;
            float xn1 = (t + 1 < TT) ? xg[t + 1 + TT] : 0.f;
            float v0[4], v1[4];
            dot4q(w, hsm[cur][0], qoff8, v0);
            dot4q(w, hsm[cur][1], qoff8, v1);
            float acc0 = combine4(v0, q0, q1) + bh;
            float acc1 = combine4(v1, q0, q1) + bh;
            float xi0 = fmaf(x0, wi, bi);
            float xi1 = fmaf(x1, wi, bi);
            float keep = 0.f;
            if (role == 0) {            // keep sig_r(b0), ship sig_r(b1)
                keep = sigfast(acc0 + xi0);
                s_g[1][unit] = sigfast(acc1 + xi1);
            } else if (role == 1) {     // keep sig_z(b1), ship sig_z(b0)
                keep = sigfast(acc1 + xi1);
                s_g[0][unit] = sigfast(acc0 + xi0);
            } else {                    // ship n-gate raw pairs
                s_n[0][unit] = make_float2(acc0, xi0);
                s_n[1][unit] = make_float2(acc1, xi1);
            }
            asm volatile("bar.sync %0, 96;" :: "r"(blk + 1) : "memory");
            if (role == 0) {            // update h(b0)
                float z0 = s_g[0][unit];
                float2 nn = s_n[0][unit];
                float n0 = tanha(fmaf(keep, nn.x, nn.y));
                hmine = fmaf(z0, hmine - n0, n0);
                hsm[cur ^ 1][0][unit] = hmine;
            } else if (role == 1) {     // update h(b1)
                float r1 = s_g[1][unit];
                float2 nn = s_n[1][unit];
                float n1 = tanha(fmaf(r1, nn.x, nn.y));
                hmine = fmaf(keep, hmine - n1, n1);
                hsm[cur ^ 1][1][unit] = hmine;
            }
            __syncthreads();
            // lag-1 publish: chunk c complete once y[128c+127] stored (top of
            // step 128(c+1)) and fenced by this barrier
            if ((t & 127) == 0 && t && tid == 0) {
                strel(fl + (t >> 7) - 1, 1);
                strel(fl + 32 + (t >> 7) - 1, 1);
            }
            x0 = xn0; x1 = xn1;
            cur ^= 1;
        }
        if (role == 2) {                         // final y[TT-1]
            yp[0] = hsm[cur][0][unit];
            yp[(size_t)TT * HH] = hsm[cur][1][unit];
        }
        __syncthreads();
        if (tid == 0) { strel(fl + 31, 1); strel(fl + 63, 1); }
        if (role == 0) hT[(size_t)b0 * HH + unit] = hmine;
        else if (role == 1) hT[(size_t)b0 * HH + HH + unit] = hmine;
    } else {
        // ======== CONSUMER: layer-1 recurrence, batches b0=2k, b0+1 ========
        const int b0 = 2 * (blockIdx.x - NPAIR);
        ull w[4][16];
#pragma unroll
        for (int r = 0; r < 4; r++)
            loadw32(w[r], w_hh1 + (size_t)(base + r) * HH + q * 32);
        const float bh = b_hh1[grow];

        float hmine = hidden[(size_t)(BB + b0 + (role == 1 ? 1 : 0)) * HH + unit];
        if (role == 0) hsm[0][0][unit] = hmine;
        else if (role == 1) hsm[0][1][unit] = hmine;

        const float* xgp0 = g_xg1 + (size_t)b0 * TT * GG + grow;
        const float* xgp1 = xgp0 + (size_t)TT * GG;
        float* yp = g_y1 + (size_t)b0 * TT * HH + unit;
        int* fl = g_flagB + b0 * 32;

        int cur = 0;
        for (int c = 0; c < 32; c++) {
            if (tid == 0) {
                while (ldacq(fl + c) == 0) __nanosleep(64);
                while (ldacq(fl + c + 32) == 0) __nanosleep(64);
            }
            __syncthreads();     // flag visible; also orders initial hsm writes
            float x0 = xgp0[(size_t)(c * 128) * GG];
            float x1 = xgp1[(size_t)(c * 128) * GG];
            for (int tt = 0; tt < 128; tt++) {
                const int t = c * 128 + tt;
                if (role == 2 && t > 0) {        // lag-1 y store
                    yp[0] = hsm[cur][0][unit];
                    yp[(size_t)TT * HH] = hsm[cur][1][unit];
                    yp += HH;
                }
                // issue next-x loads FIRST so latency hides under the dots
                float xn0 = (tt < 127) ? xgp0[(size_t)(t + 1) * GG] : 0.f;
                float xn1 = (tt < 127) ? xgp1[(size_t)(t + 1) * GG] : 0.f;
                float v0[4], v1[4];
                dot4q(w, hsm[cur][0], qoff8, v0);
                dot4q(w, hsm[cur][1], qoff8, v1);
                float acc0 = combine4(v0, q0, q1) + bh;
                float acc1 = combine4(v1, q0, q1) + bh;
                float keep = 0.f;
                if (role == 0) {
                    keep = sigfast(acc0 + x0);
                    s_g[1][unit] = sigfast(acc1 + x1);
                } else if (role == 1) {
                    keep = sigfast(acc1 + x1);
                    s_g[0][unit] = sigfast(acc0 + x0);
                } else {
                    s_n[0][unit] = make_float2(acc0, x0);
                    s_n[1][unit] = make_float2(acc1, x1);
                }
                asm volatile("bar.sync %0, 96;" :: "r"(blk + 1) : "memory");
                if (role == 0) {
                    float z0 = s_g[0][unit];
                    float2 nn = s_n[0][unit];
                    float n0 = tanha(fmaf(keep, nn.x, nn.y));
                    hmine = fmaf(z0, hmine - n0, n0);
                    hsm[cur ^ 1][0][unit] = hmine;
                } else if (role == 1) {
                    float r1 = s_g[1][unit];
                    float2 nn = s_n[1][unit];
                    float n1 = tanha(fmaf(r1, nn.x, nn.y));
                    hmine = fmaf(keep, hmine - n1, n1);
                    hsm[cur ^ 1][1][unit] = hmine;
                }
                __syncthreads();
                x0 = xn0; x1 = xn1;
                cur ^= 1;
            }
            if (tid == 0) {                     // self-reset for next replay
                stplain(fl + c, 0);
                stplain(fl + c + 32, 0);
            }
        }
        if (role == 2) {                         // final y[TT-1]
            yp[0] = hsm[cur][0][unit];
            yp[(size_t)TT * HH] = hsm[cur][1][unit];
        }
        if (role == 0) hT[(size_t)(BB + b0) * HH + unit] = hmine;
        else if (role == 1) hT[(size_t)(BB + b0) * HH + HH + unit] = hmine;
    }
}

// ---------- Tail: out[b,t] = relu(y1[b,t,:]) . fc_w + fc_b  (memory-bound) ----------
__global__ void __launch_bounds__(256)
k_fc(const float* __restrict__ fc_w, const float* __restrict__ fc_b,
     float* __restrict__ out) {
    const int row = blockIdx.x * 8 + (threadIdx.x >> 5);   // row = b*TT + t
    const int lane = threadIdx.x & 31;
    float4 yv = ((const float4*)(g_y1 + (size_t)row * HH))[lane];
    float4 wv = ((const float4*)fc_w)[lane];
    float p = fmaxf(yv.x, 0.f) * wv.x + fmaxf(yv.y, 0.f) * wv.y
            + fmaxf(yv.z, 0.f) * wv.z + fmaxf(yv.w, 0.f) * wv.w;
    p += __shfl_xor_sync(0xffffffffu, p, 16);
    p += __shfl_xor_sync(0xffffffffu, p, 8);
    p += __shfl_xor_sync(0xffffffffu, p, 4);
    p += __shfl_xor_sync(0xffffffffu, p, 2);
    p += __shfl_xor_sync(0xffffffffu, p, 1);
    if (lane == 0) out[row] = p + fc_b[0];
}

extern "C" void kernel_launch(void* const* d_in, const int* in_sizes, int n_in,
                              void* d_out, int out_size) {
    const float* data   = (const float*)d_in[0];
    const float* hidden = (const float*)d_in[1];
    const float* w_ih0  = (const float*)d_in[2];
    const float* w_hh0  = (const float*)d_in[3];
    const float* b_ih0  = (const float*)d_in[4];
    const float* b_hh0  = (const float*)d_in[5];
    const float* w_ih1  = (const float*)d_in[6];
    const float* w_hh1  = (const float*)d_in[7];
    const float* b_ih1  = (const float*)d_in[8];
    const float* b_hh1  = (const float*)d_in[9];
    const float* fc_w   = (const float*)d_in[10];
    const float* fc_b   = (const float*)d_in[11];

    float* out = (float*)d_out;
    float* hT  = out + (size_t)BB * TT;   // [2,B,H] final hidden

    k_main<<<2 * NPAIR + NWORK, 384>>>(data, hidden, w_ih0, w_hh0, b_ih0, b_hh0,
                                       w_ih1, w_hh1, b_ih1, b_hh1, hT);
    k_fc<<<BB * TT / 8, 256>>>(fc_w, fc_b, out);
}

// round 14
// speedup vs baseline: 1.0652x; 1.0524x over previous
#include <cuda_runtime.h>

#define BB 64
#define TT 4096
#define HH 128
#define GG 384    /* 3H */
#define NPAIR 32  /* producer/consumer CTAs each handle 2 batches */
#define NWORK 84  /* GEMM workers; 32+32+84 = 148 = full wave-1 residency */

// Scratch (allocation-free rule: __device__ globals)
__device__ float g_y0[(size_t)BB * TT * HH];    // layer-0 outputs [b][t][k]  128 MiB
__device__ float g_xg1[(size_t)BB * TT * GG];   // layer-1 ih gates [b][t][g] 402 MiB
__device__ float g_y1[(size_t)BB * TT * HH];    // layer-1 outputs [b][t][k]  128 MiB
__device__ int   g_flagA[BB * 32];              // y0 chunk ready  (producer -> worker)
__device__ int   g_flagB[BB * 32];              // xg1 chunk ready (worker -> consumer)

typedef unsigned long long ull;

static __device__ __forceinline__ ull pk(float a, float b) {
    ull r; asm("mov.b64 %0, {%1, %2};" : "=l"(r) : "f"(a), "f"(b)); return r;
}
static __device__ __forceinline__ void upk(ull v, float& a, float& b) {
    asm("mov.b64 {%0, %1}, %2;" : "=f"(a), "=f"(b) : "l"(v));
}
// Packed fp32x2 FMA / ADD (Blackwell): 2 ops per issue slot
static __device__ __forceinline__ void ffma2(ull& acc, ull a, ull b) {
    asm("fma.rn.f32x2 %0, %1, %2, %0;" : "+l"(acc) : "l"(a), "l"(b));
}
static __device__ __forceinline__ ull add2(ull a, ull b) {
    ull r; asm("add.rn.f32x2 %0, %1, %2;" : "=l"(r) : "l"(a), "l"(b)); return r;
}
static __device__ __forceinline__ float red2(ull a, ull b) {
    ull s = add2(a, b); float x0, x1; upk(s, x0, x1); return x0 + x1;
}
static __device__ __forceinline__ float tanha(float x) {     // MUFU tanh
    float y; asm("tanh.approx.f32 %0, %1;" : "=f"(y) : "f"(x)); return y;
}
static __device__ __forceinline__ float sigfast(float x) {   // sigmoid via MUFU tanh
    return fmaf(0.5f, tanha(0.5f * x), 0.5f);
}
static __device__ __forceinline__ int ldacq(const int* p) {
    int v; asm volatile("ld.acquire.gpu.global.b32 %0, [%1];" : "=r"(v) : "l"(p) : "memory");
    return v;
}
static __device__ __forceinline__ void strel(int* p, int v) {
    asm volatile("st.release.gpu.global.b32 [%0], %1;" :: "l"(p), "r"(v) : "memory");
}
static __device__ __forceinline__ void stplain(int* p, int v) {
    asm volatile("st.global.b32 [%0], %1;" :: "l"(p), "r"(v) : "memory");
}

// Load one full 128-float weight row into 64 packed pairs (worker path).
static __device__ __forceinline__ void loadw(ull* w, const float* __restrict__ row) {
    const float4* r4 = (const float4*)row;
#pragma unroll
    for (int i = 0; i < 32; i++) {
        float4 v = r4[i];
        w[2 * i]     = pk(v.x, v.y);
        w[2 * i + 1] = pk(v.z, v.w);
    }
}
// Load a 32-float quarter-row into 16 packed pairs (recurrence path).
static __device__ __forceinline__ void loadw32(ull* w, const float* __restrict__ row) {
    const float4* r4 = (const float4*)row;
#pragma unroll
    for (int i = 0; i < 8; i++) {
        float4 v = r4[i];
        w[2 * i]     = pk(v.x, v.y);
        w[2 * i + 1] = pk(v.z, v.w);
    }
}

// Full dot (worker path): 32 LDS.128 + 64 FFMA2, 4 chains.
static __device__ __forceinline__ float dot128(const ull* w, const float* hsm) {
    const ulonglong2* h2 = (const ulonglong2*)hsm;
    ull a0 = 0, a1 = 0, a2 = 0, a3 = 0;
#pragma unroll
    for (int k = 0; k < 16; k++) {
        ulonglong2 p = h2[2 * k];
        ulonglong2 q = h2[2 * k + 1];
        ffma2(a0, w[4 * k + 0], p.x);
        ffma2(a1, w[4 * k + 1], p.y);
        ffma2(a2, w[4 * k + 2], q.x);
        ffma2(a3, w[4 * k + 3], q.y);
    }
    return red2(add2(a0, a1), add2(a2, a3));
}

// Recurrence dot: this thread's QUARTER of h (8 LDS.128) feeding FOUR adjacent
// rows' quarter-dots (4 independent chains, 16 FFMA2 each).
static __device__ __forceinline__ void dot4q(const ull w[4][16], const float* hsm,
                                             int qoff8, float* v) {
    const ulonglong2* h2 = (const ulonglong2*)hsm + qoff8;   // quarter q: +8q
    ull a0 = 0, a1 = 0, a2 = 0, a3 = 0;
#pragma unroll
    for (int k = 0; k < 8; k++) {
        ulonglong2 q = h2[k];
        ffma2(a0, w[0][2 * k], q.x); ffma2(a0, w[0][2 * k + 1], q.y);
        ffma2(a1, w[1][2 * k], q.x); ffma2(a1, w[1][2 * k + 1], q.y);
        ffma2(a2, w[2][2 * k], q.x); ffma2(a2, w[2][2 * k + 1], q.y);
        ffma2(a3, w[3][2 * k], q.x); ffma2(a3, w[3][2 * k + 1], q.y);
    }
    float x0, x1;
    upk(a0, x0, x1); v[0] = x0 + x1;
    upk(a1, x0, x1); v[1] = x0 + x1;
    upk(a2, x0, x1); v[2] = x0 + x1;
    upk(a3, x0, x1); v[3] = x0 + x1;
}

// Combine 4 quarter-dots across lanes {j, j+8, j+16, j+24} (2 butterfly
// rounds). Lane (q1,q0) ends with the FULL dot of row base+4j+2*q1+q0.
static __device__ __forceinline__ float combine4(const float* v, int q0, int q1) {
    float s_lo = q0 ? v[0] : v[1];
    float k_lo = q0 ? v[1] : v[0];
    float s_hi = q0 ? v[2] : v[3];
    float k_hi = q0 ? v[3] : v[2];
    float u0 = k_lo + __shfl_xor_sync(0xffffffffu, s_lo, 8);
    float u1 = k_hi + __shfl_xor_sync(0xffffffffu, s_hi, 8);
    float s2 = q1 ? u0 : u1;
    float k2 = q1 ? u1 : u0;
    return k2 + __shfl_xor_sync(0xffffffffu, s2, 16);
}

// ===== Wavefront mega-kernel with 2-batch-interleaved recurrences =====
//   CTA 0..31  : layer-0 producer for batches (2k, 2k+1)
//   CTA 32..63 : layer-1 consumer for batches (2k, 2k+1), chunk-gated on flagB
//   CTA 64..147: 84 GEMM workers (flagA -> xg1 chunk -> flagB)
// IDENTICAL logic to the round-11 winner; the ONLY change is the register
// diet: every per-batch pointer pair is ONE base pointer + compile-time
// immediate offset (TT, TT*HH, TT*GG, 32), and all hot-loop offsets are
// 32-bit ints advanced by IADD (ALU pipe, no size_t IMAD chains).
__global__ void __launch_bounds__(384, 1)
k_main(const float* __restrict__ data, const float* __restrict__ hidden,
       const float* __restrict__ w_ih0, const float* __restrict__ w_hh0,
       const float* __restrict__ b_ih0, const float* __restrict__ b_hh0,
       const float* __restrict__ w_ih1, const float* __restrict__ w_hh1,
       const float* __restrict__ b_ih1, const float* __restrict__ b_hh1,
       float* __restrict__ hT) {
    __shared__ __align__(16) float hsm[2][2][HH];    // [buf][batch][unit]
    __shared__ __align__(8) float2 s_rz[2][HH];      // [batch][unit]
    __shared__ __align__(16) float ybuf[8 * HH];

    const int tid = threadIdx.x;

    if (blockIdx.x >= 2 * NPAIR) {
        // ---------------- WORKER: xg1 = y0 @ w_ih1.T + b_ih1 ----------------
        const int wk = blockIdx.x - 2 * NPAIR;
        ull w[64];
        loadw(w, w_ih1 + tid * HH);
        const float bi = b_ih1[tid];

        for (int task = wk; task < BB * 32; task += NWORK) {
            const int c = task >> 6, b = task & 63;   // chunk-major = production order
            if (tid == 0) {
                const int* f = g_flagA + b * 32 + c;
                while (ldacq(f) == 0) __nanosleep(64);
            }
            __syncthreads();
            const float* y0 = g_y0 + ((size_t)b * TT + (size_t)c * 128) * HH;
            float* xo = g_xg1 + ((size_t)b * TT + (size_t)c * 128) * GG;
            for (int tt = 0; tt < 128; tt += 8) {
                if (tid < 256) ((float4*)ybuf)[tid] = ((const float4*)(y0 + (size_t)tt * HH))[tid];
                __syncthreads();
#pragma unroll
                for (int r = 0; r < 8; r++) {
                    float acc = dot128(w, ybuf + r * HH);
                    xo[(size_t)(tt + r) * GG + tid] = acc + bi;
                }
                __syncthreads();
            }
            if (tid == 0) {
                stplain(g_flagA + b * 32 + c, 0);     // self-reset for next replay
                strel(g_flagB + b * 32 + c, 1);
            }
        }
        return;
    }

    const int warp = tid >> 5, lane = tid & 31;
    const int role = warp >> 2;            // 0=r, 1=z, 2=n
    const int blk  = warp & 3;
    const int q    = lane >> 3;
    const int q0   = q & 1, q1 = q >> 1;
    const int j    = lane & 7;
    const int base = (role << 7) | (blk << 5) | (j << 2);
    const int unit = (blk << 5) | (j << 2) | (q1 << 1) | q0;
    const int grow = (role << 7) | unit;
    const int qoff8 = q << 3;

    if (blockIdx.x < NPAIR) {
        // ======== PRODUCER: layer-0 recurrence, batches b0=2k, b0+1 ========
        const int b0 = 2 * blockIdx.x;
        ull w[4][16];
#pragma unroll
        for (int r = 0; r < 4; r++)
            loadw32(w[r], w_hh0 + (size_t)(base + r) * HH + q * 32);
        const float wi = w_ih0[grow], bi = b_ih0[grow], bh = b_hh0[grow];

        float h0 = hidden[b0 * HH + unit];
        float h1 = hidden[b0 * HH + HH + unit];
        if (role == 2) { hsm[0][0][unit] = h0; hsm[0][1][unit] = h1; }
        __syncthreads();

        const float* xg = data + b0 * TT;                // batch1 at +TT (imm)
        float* yp = g_y0 + (size_t)b0 * TT * HH + unit;  // batch1 at +TT*HH (imm)
        int* fl = g_flagA + b0 * 32;                     // batch1 at +32 (imm)

        int cur = 0;
        float x0 = xg[0], x1 = xg[TT];
        for (int t = 0; t < TT; t++) {
            float xn0 = (t + 1 < TT) ? xg[t + 1] : 0.f;
            float xn1 = (t + 1 < TT) ? xg[t + 1 + TT] : 0.f;
            float v0[4], v1[4];
            dot4q(w, hsm[cur][0], qoff8, v0);
            dot4q(w, hsm[cur][1], qoff8, v1);
            float acc0 = combine4(v0, q0, q1) + bh;
            float acc1 = combine4(v1, q0, q1) + bh;
            float xi0 = fmaf(x0, wi, bi);
            float xi1 = fmaf(x1, wi, bi);
            if (role == 0) {
                s_rz[0][unit].x = sigfast(acc0 + xi0);
                s_rz[1][unit].x = sigfast(acc1 + xi1);
            } else if (role == 1) {
                s_rz[0][unit].y = sigfast(acc0 + xi0);
                s_rz[1][unit].y = sigfast(acc1 + xi1);
            }
            asm volatile("bar.sync %0, 96;" :: "r"(blk + 1) : "memory");
            if (role == 2) {
                float2 rz0 = s_rz[0][unit];
                float2 rz1 = s_rz[1][unit];
                float n0 = tanha(fmaf(rz0.x, acc0, xi0));
                float n1 = tanha(fmaf(rz1.x, acc1, xi1));
                h0 = fmaf(rz0.y, h0 - n0, n0);
                h1 = fmaf(rz1.y, h1 - n1, n1);
                hsm[cur ^ 1][0][unit] = h0;
                hsm[cur ^ 1][1][unit] = h1;
                yp[0] = h0;
                yp[TT * HH] = h1;     // immediate offset, no second pointer
            }
            __syncthreads();
            if (((t & 127) == 127) && tid == 0) {   // publish both chunks
                strel(fl + (t >> 7), 1);
                strel(fl + 32 + (t >> 7), 1);
            }
            x0 = xn0; x1 = xn1;
            yp += HH;
            cur ^= 1;
        }
        if (role == 2) {
            hT[b0 * HH + unit] = h0;
            hT[b0 * HH + HH + unit] = h1;
        }
    } else {
        // ======== CONSUMER: layer-1 recurrence, batches b0=2k, b0+1 ========
        const int b0 = 2 * (blockIdx.x - NPAIR);
        ull w[4][16];
#pragma unroll
        for (int r = 0; r < 4; r++)
            loadw32(w[r], w_hh1 + (size_t)(base + r) * HH + q * 32);
        const float bh = b_hh1[grow];

        float h0 = hidden[(BB + b0) * HH + unit];
        float h1 = hidden[(BB + b0) * HH + HH + unit];
        if (role == 2) { hsm[0][0][unit] = h0; hsm[0][1][unit] = h1; }

        const float* xg = g_xg1 + (size_t)b0 * TT * GG + grow;  // batch1 at +TT*GG (imm)
        float* yp = g_y1 + (size_t)b0 * TT * HH + unit;         // batch1 at +TT*HH (imm)
        int* fl = g_flagB + b0 * 32;                            // batch1 at +32 (imm)

        int cur = 0;
        for (int c = 0; c < 32; c++) {
            if (tid == 0) {
                while (ldacq(fl + c) == 0) __nanosleep(64);
                while (ldacq(fl + c + 32) == 0) __nanosleep(64);
            }
            __syncthreads();     // flag visible; also orders initial hsm writes
            int xo = c * 128 * GG;                // int offset, advances by GG
            float x0 = xg[xo], x1 = xg[xo + TT * GG];
            for (int tt = 0; tt < 128; tt++) {
                // issue next-x loads FIRST so latency hides under the dots
                float xn0 = (tt < 127) ? xg[xo + GG] : 0.f;
                float xn1 = (tt < 127) ? xg[xo + GG + TT * GG] : 0.f;
                float v0[4], v1[4];
                dot4q(w, hsm[cur][0], qoff8, v0);
                dot4q(w, hsm[cur][1], qoff8, v1);
                float acc0 = combine4(v0, q0, q1) + bh;
                float acc1 = combine4(v1, q0, q1) + bh;
                if (role == 0) {
                    s_rz[0][unit].x = sigfast(acc0 + x0);
                    s_rz[1][unit].x = sigfast(acc1 + x1);
                } else if (role == 1) {
                    s_rz[0][unit].y = sigfast(acc0 + x0);
                    s_rz[1][unit].y = sigfast(acc1 + x1);
                }
                asm volatile("bar.sync %0, 96;" :: "r"(blk + 1) : "memory");
                if (role == 2) {
                    float2 rz0 = s_rz[0][unit];
                    float2 rz1 = s_rz[1][unit];
                    float n0 = tanha(fmaf(rz0.x, acc0, x0));
                    float n1 = tanha(fmaf(rz1.x, acc1, x1));
                    h0 = fmaf(rz0.y, h0 - n0, n0);
                    h1 = fmaf(rz1.y, h1 - n1, n1);
                    hsm[cur ^ 1][0][unit] = h0;
                    hsm[cur ^ 1][1][unit] = h1;
                    yp[0] = h0;
                    yp[TT * HH] = h1;
                }
                __syncthreads();
                x0 = xn0; x1 = xn1;
                xo += GG;
                yp += HH;
                cur ^= 1;
            }
            if (tid == 0) {                     // self-reset for next replay
                stplain(fl + c, 0);
                stplain(fl + c + 32, 0);
            }
        }
        if (role == 2) {
            hT[(BB + b0) * HH + unit] = h0;
            hT[(BB + b0) * HH + HH + unit] = h1;
        }
    }
}

// ---------- Tail: out[b,t] = relu(y1[b,t,:]) . fc_w + fc_b  (memory-bound) ----------
__global__ void __launch_bounds__(256)
k_fc(const float* __restrict__ fc_w, const float* __restrict__ fc_b,
     float* __restrict__ out) {
    const int row = blockIdx.x * 8 + (threadIdx.x >> 5);   // row = b*TT + t
    const int lane = threadIdx.x & 31;
    float4 yv = ((const float4*)(g_y1 + (size_t)row * HH))[lane];
    float4 wv = ((const float4*)fc_w)[lane];
    float p = fmaxf(yv.x, 0.f) * wv.x + fmaxf(yv.y, 0.f) * wv.y
            + fmaxf(yv.z, 0.f) * wv.z + fmaxf(yv.w, 0.f) * wv.w;
    p += __shfl_xor_sync(0xffffffffu, p, 16);
    p += __shfl_xor_sync(0xffffffffu, p, 8);
    p += __shfl_xor_sync(0xffffffffu, p, 4);
    p += __shfl_xor_sync(0xffffffffu, p, 2);
    p += __shfl_xor_sync(0xffffffffu, p, 1);
    if (lane == 0) out[row] = p + fc_b[0];
}

extern "C" void kernel_launch(void* const* d_in, const int* in_sizes, int n_in,
                              void* d_out, int out_size) {
    const float* data   = (const float*)d_in[0];
    const float* hidden = (const float*)d_in[1];
    const float* w_ih0  = (const float*)d_in[2];
    const float* w_hh0  = (const float*)d_in[3];
    const float* b_ih0  = (const float*)d_in[4];
    const float* b_hh0  = (const float*)d_in[5];
    const float* w_ih1  = (const float*)d_in[6];
    const float* w_hh1  = (const float*)d_in[7];
    const float* b_ih1  = (const float*)d_in[8];
    const float* b_hh1  = (const float*)d_in[9];
    const float* fc_w   = (const float*)d_in[10];
    const float* fc_b   = (const float*)d_in[11];

    float* out = (float*)d_out;
    float* hT  = out + (size_t)BB * TT;   // [2,B,H] final hidden

    k_main<<<2 * NPAIR + NWORK, 384>>>(data, hidden, w_ih0, w_hh0, b_ih0, b_hh0,
                                       w_ih1, w_hh1, b_ih1, b_hh1, hT);
    k_fc<<<BB * TT / 8, 256>>>(fc_w, fc_b, out);
}

// round 15
// speedup vs baseline: 1.0883x; 1.0216x over previous
#include <cuda_runtime.h>

#define BB 64
#define TT 4096
#define HH 128
#define GG 384    /* 3H */
#define NPAIR 32  /* producer/consumer CTAs each handle 2 batches */
#define NWORK 84  /* GEMM workers; 32+32+84 = 148 = full wave-1 residency */
#define HPLANE 144 /* padded h plane: 4 quarters x 36 floats -> bank-disjoint */

// Scratch (allocation-free rule: __device__ globals)
__device__ float g_y0[(size_t)BB * TT * HH];    // layer-0 outputs [b][t][k]  128 MiB
__device__ float g_xg1[(size_t)BB * TT * GG];   // layer-1 ih gates [b][t][g] 402 MiB
__device__ float g_y1[(size_t)BB * TT * HH];    // layer-1 outputs [b][t][k]  128 MiB
__device__ int   g_flagA[BB * 32];              // y0 chunk ready  (producer -> worker)
__device__ int   g_flagB[BB * 32];              // xg1 chunk ready (worker -> consumer)

typedef unsigned long long ull;

static __device__ __forceinline__ ull pk(float a, float b) {
    ull r; asm("mov.b64 %0, {%1, %2};" : "=l"(r) : "f"(a), "f"(b)); return r;
}
static __device__ __forceinline__ void upk(ull v, float& a, float& b) {
    asm("mov.b64 {%0, %1}, %2;" : "=f"(a), "=f"(b) : "l"(v));
}
// Packed fp32x2 FMA / ADD (Blackwell): 2 ops per issue slot
static __device__ __forceinline__ void ffma2(ull& acc, ull a, ull b) {
    asm("fma.rn.f32x2 %0, %1, %2, %0;" : "+l"(acc) : "l"(a), "l"(b));
}
static __device__ __forceinline__ ull add2(ull a, ull b) {
    ull r; asm("add.rn.f32x2 %0, %1, %2;" : "=l"(r) : "l"(a), "l"(b)); return r;
}
static __device__ __forceinline__ float red2(ull a, ull b) {
    ull s = add2(a, b); float x0, x1; upk(s, x0, x1); return x0 + x1;
}
static __device__ __forceinline__ float tanha(float x) {     // MUFU tanh
    float y; asm("tanh.approx.f32 %0, %1;" : "=f"(y) : "f"(x)); return y;
}
static __device__ __forceinline__ float sigfast(float x) {   // sigmoid via MUFU tanh
    return fmaf(0.5f, tanha(0.5f * x), 0.5f);
}
static __device__ __forceinline__ int ldacq(const int* p) {
    int v; asm volatile("ld.acquire.gpu.global.b32 %0, [%1];" : "=r"(v) : "l"(p) : "memory");
    return v;
}
static __device__ __forceinline__ void strel(int* p, int v) {
    asm volatile("st.release.gpu.global.b32 [%0], %1;" :: "l"(p), "r"(v) : "memory");
}
static __device__ __forceinline__ void stplain(int* p, int v) {
    asm volatile("st.global.b32 [%0], %1;" :: "l"(p), "r"(v) : "memory");
}

// Load one full 128-float weight row into 64 packed pairs (worker path).
static __device__ __forceinline__ void loadw(ull* w, const float* __restrict__ row) {
    const float4* r4 = (const float4*)row;
#pragma unroll
    for (int i = 0; i < 32; i++) {
        float4 v = r4[i];
        w[2 * i]     = pk(v.x, v.y);
        w[2 * i + 1] = pk(v.z, v.w);
    }
}
// Load a 32-float quarter-row into 16 packed pairs (recurrence path).
static __device__ __forceinline__ void loadw32(ull* w, const float* __restrict__ row) {
    const float4* r4 = (const float4*)row;
#pragma unroll
    for (int i = 0; i < 8; i++) {
        float4 v = r4[i];
        w[2 * i]     = pk(v.x, v.y);
        w[2 * i + 1] = pk(v.z, v.w);
    }
}

// Full dot (worker path): 32 LDS.128 (pure broadcast, conflict-free) + 64 FFMA2.
static __device__ __forceinline__ float dot128(const ull* w, const float* hsm) {
    const ulonglong2* h2 = (const ulonglong2*)hsm;
    ull a0 = 0, a1 = 0, a2 = 0, a3 = 0;
#pragma unroll
    for (int k = 0; k < 16; k++) {
        ulonglong2 p = h2[2 * k];
        ulonglong2 q = h2[2 * k + 1];
        ffma2(a0, w[4 * k + 0], p.x);
        ffma2(a1, w[4 * k + 1], p.y);
        ffma2(a2, w[4 * k + 2], q.x);
        ffma2(a3, w[4 * k + 3], q.y);
    }
    return red2(add2(a0, a1), add2(a2, a3));
}

// Recurrence dot on the PADDED h plane: this thread's QUARTER (8 LDS.128,
// quarter bases 144B apart -> bank-disjoint, conflict-free) feeding FOUR
// adjacent rows' quarter-dots (4 independent chains, 16 FFMA2 each).
static __device__ __forceinline__ void dot4q(const ull w[4][16], const float* hplane,
                                             int qoff9, float* v) {
    const ulonglong2* h2 = (const ulonglong2*)hplane + qoff9;   // quarter q: +9q
    ull a0 = 0, a1 = 0, a2 = 0, a3 = 0;
#pragma unroll
    for (int k = 0; k < 8; k++) {
        ulonglong2 q = h2[k];
        ffma2(a0, w[0][2 * k], q.x); ffma2(a0, w[0][2 * k + 1], q.y);
        ffma2(a1, w[1][2 * k], q.x); ffma2(a1, w[1][2 * k + 1], q.y);
        ffma2(a2, w[2][2 * k], q.x); ffma2(a2, w[2][2 * k + 1], q.y);
        ffma2(a3, w[3][2 * k], q.x); ffma2(a3, w[3][2 * k + 1], q.y);
    }
    float x0, x1;
    upk(a0, x0, x1); v[0] = x0 + x1;
    upk(a1, x0, x1); v[1] = x0 + x1;
    upk(a2, x0, x1); v[2] = x0 + x1;
    upk(a3, x0, x1); v[3] = x0 + x1;
}

// Combine 4 quarter-dots across lanes {j, j+8, j+16, j+24} (2 butterfly
// rounds). Lane (q1,q0) ends with the FULL dot of row base+4j+2*q1+q0.
static __device__ __forceinline__ float combine4(const float* v, int q0, int q1) {
    float s_lo = q0 ? v[0] : v[1];
    float k_lo = q0 ? v[1] : v[0];
    float s_hi = q0 ? v[2] : v[3];
    float k_hi = q0 ? v[3] : v[2];
    float u0 = k_lo + __shfl_xor_sync(0xffffffffu, s_lo, 8);
    float u1 = k_hi + __shfl_xor_sync(0xffffffffu, s_hi, 8);
    float s2 = q1 ? u0 : u1;
    float k2 = q1 ? u1 : u0;
    return k2 + __shfl_xor_sync(0xffffffffu, s2, 16);
}

// ===== Wavefront mega-kernel with 2-batch-interleaved recurrences =====
//   CTA 0..31  : layer-0 producer for batches (2k, 2k+1)
//   CTA 32..63 : layer-1 consumer for batches (2k, 2k+1), chunk-gated on flagB
//   CTA 64..147: 84 GEMM workers (flagA -> xg1 chunk -> flagB)
// IDENTICAL logic to the round-14 winner; the ONLY change is the padded h
// layout: unit u lives at plane index 36*(u>>5) + (u&31) (HPLANE=144), which
// makes the four quarter-broadcast LDS streams bank-disjoint (was a 4-way
// conflict serializing every dot4q load into 4 crossbar phases).
__global__ void __launch_bounds__(384, 1)
k_main(const float* __restrict__ data, const float* __restrict__ hidden,
       const float* __restrict__ w_ih0, const float* __restrict__ w_hh0,
       const float* __restrict__ b_ih0, const float* __restrict__ b_hh0,
       const float* __restrict__ w_ih1, const float* __restrict__ w_hh1,
       const float* __restrict__ b_ih1, const float* __restrict__ b_hh1,
       float* __restrict__ hT) {
    __shared__ __align__(16) float hsm[2][2][HPLANE];  // [buf][batch][padded unit]
    __shared__ __align__(8) float2 s_rz[2][HH];        // [batch][unit]
    __shared__ __align__(16) float ybuf[8 * HH];

    const int tid = threadIdx.x;

    if (blockIdx.x >= 2 * NPAIR) {
        // ---------------- WORKER: xg1 = y0 @ w_ih1.T + b_ih1 ----------------
        const int wk = blockIdx.x - 2 * NPAIR;
        ull w[64];
        loadw(w, w_ih1 + tid * HH);
        const float bi = b_ih1[tid];

        for (int task = wk; task < BB * 32; task += NWORK) {
            const int c = task >> 6, b = task & 63;   // chunk-major = production order
            if (tid == 0) {
                const int* f = g_flagA + b * 32 + c;
                while (ldacq(f) == 0) __nanosleep(64);
            }
            __syncthreads();
            const float* y0 = g_y0 + ((size_t)b * TT + (size_t)c * 128) * HH;
            float* xo = g_xg1 + ((size_t)b * TT + (size_t)c * 128) * GG;
            for (int tt = 0; tt < 128; tt += 8) {
                if (tid < 256) ((float4*)ybuf)[tid] = ((const float4*)(y0 + (size_t)tt * HH))[tid];
                __syncthreads();
#pragma unroll
                for (int r = 0; r < 8; r++) {
                    float acc = dot128(w, ybuf + r * HH);
                    xo[(size_t)(tt + r) * GG + tid] = acc + bi;
                }
                __syncthreads();
            }
            if (tid == 0) {
                stplain(g_flagA + b * 32 + c, 0);     // self-reset for next replay
                strel(g_flagB + b * 32 + c, 1);
            }
        }
        return;
    }

    const int warp = tid >> 5, lane = tid & 31;
    const int role = warp >> 2;            // 0=r, 1=z, 2=n
    const int blk  = warp & 3;
    const int q    = lane >> 3;
    const int q0   = q & 1, q1 = q >> 1;
    const int j    = lane & 7;
    const int base = (role << 7) | (blk << 5) | (j << 2);
    const int unit = (blk << 5) | (j << 2) | (q1 << 1) | q0;
    const int grow = (role << 7) | unit;
    const int qoff9 = q * 9;                       // ulonglong2 offset of padded quarter
    const int hidx = blk * 36 + ((j << 2) | (q1 << 1) | q0);   // padded index of 'unit'

    if (blockIdx.x < NPAIR) {
        // ======== PRODUCER: layer-0 recurrence, batches b0=2k, b0+1 ========
        const int b0 = 2 * blockIdx.x;
        ull w[4][16];
#pragma unroll
        for (int r = 0; r < 4; r++)
            loadw32(w[r], w_hh0 + (size_t)(base + r) * HH + q * 32);
        const float wi = w_ih0[grow], bi = b_ih0[grow], bh = b_hh0[grow];

        float h0 = hidden[b0 * HH + unit];
        float h1 = hidden[b0 * HH + HH + unit];
        if (role == 2) { hsm[0][0][hidx] = h0; hsm[0][1][hidx] = h1; }
        __syncthreads();

        const float* xg = data + b0 * TT;                // batch1 at +TT (imm)
        float* yp = g_y0 + (size_t)b0 * TT * HH + unit;  // batch1 at +TT*HH (imm)
        int* fl = g_flagA + b0 * 32;                     // batch1 at +32 (imm)

        int cur = 0;
        float x0 = xg[0], x1 = xg[TT];
        for (int t = 0; t < TT; t++) {
            float xn0 = (t + 1 < TT) ? xg[t + 1] : 0.f;
            float xn1 = (t + 1 < TT) ? xg[t + 1 + TT] : 0.f;
            float v0[4], v1[4];
            dot4q(w, hsm[cur][0], qoff9, v0);
            dot4q(w, hsm[cur][1], qoff9, v1);
            float acc0 = combine4(v0, q0, q1) + bh;
            float acc1 = combine4(v1, q0, q1) + bh;
            float xi0 = fmaf(x0, wi, bi);
            float xi1 = fmaf(x1, wi, bi);
            if (role == 0) {
                s_rz[0][unit].x = sigfast(acc0 + xi0);
                s_rz[1][unit].x = sigfast(acc1 + xi1);
            } else if (role == 1) {
                s_rz[0][unit].y = sigfast(acc0 + xi0);
                s_rz[1][unit].y = sigfast(acc1 + xi1);
            }
            asm volatile("bar.sync %0, 96;" :: "r"(blk + 1) : "memory");
            if (role == 2) {
                float2 rz0 = s_rz[0][unit];
                float2 rz1 = s_rz[1][unit];
                float n0 = tanha(fmaf(rz0.x, acc0, xi0));
                float n1 = tanha(fmaf(rz1.x, acc1, xi1));
                h0 = fmaf(rz0.y, h0 - n0, n0);
                h1 = fmaf(rz1.y, h1 - n1, n1);
                hsm[cur ^ 1][0][hidx] = h0;
                hsm[cur ^ 1][1][hidx] = h1;
                yp[0] = h0;
                yp[TT * HH] = h1;     // immediate offset, no second pointer
            }
            __syncthreads();
            if (((t & 127) == 127) && tid == 0) {   // publish both chunks
                strel(fl + (t >> 7), 1);
                strel(fl + 32 + (t >> 7), 1);
            }
            x0 = xn0; x1 = xn1;
            yp += HH;
            cur ^= 1;
        }
        if (role == 2) {
            hT[b0 * HH + unit] = h0;
            hT[b0 * HH + HH + unit] = h1;
        }
    } else {
        // ======== CONSUMER: layer-1 recurrence, batches b0=2k, b0+1 ========
        const int b0 = 2 * (blockIdx.x - NPAIR);
        ull w[4][16];
#pragma unroll
        for (int r = 0; r < 4; r++)
            loadw32(w[r], w_hh1 + (size_t)(base + r) * HH + q * 32);
        const float bh = b_hh1[grow];

        float h0 = hidden[(BB + b0) * HH + unit];
        float h1 = hidden[(BB + b0) * HH + HH + unit];
        if (role == 2) { hsm[0][0][hidx] = h0; hsm[0][1][hidx] = h1; }

        const float* xg = g_xg1 + (size_t)b0 * TT * GG + grow;  // batch1 at +TT*GG (imm)
        float* yp = g_y1 + (size_t)b0 * TT * HH + unit;         // batch1 at +TT*HH (imm)
        int* fl = g_flagB + b0 * 32;                            // batch1 at +32 (imm)

        int cur = 0;
        for (int c = 0; c < 32; c++) {
            if (tid == 0) {
                while (ldacq(fl + c) == 0) __nanosleep(64);
                while (ldacq(fl + c + 32) == 0) __nanosleep(64);
            }
            __syncthreads();     // flag visible; also orders initial hsm writes
            int xo = c * 128 * GG;                // int offset, advances by GG
            float x0 = xg[xo], x1 = xg[xo + TT * GG];
            for (int tt = 0; tt < 128; tt++) {
                // issue next-x loads FIRST so latency hides under the dots
                float xn0 = (tt < 127) ? xg[xo + GG] : 0.f;
                float xn1 = (tt < 127) ? xg[xo + GG + TT * GG] : 0.f;
                float v0[4], v1[4];
                dot4q(w, hsm[cur][0], qoff9, v0);
                dot4q(w, hsm[cur][1], qoff9, v1);
                float acc0 = combine4(v0, q0, q1) + bh;
                float acc1 = combine4(v1, q0, q1) + bh;
                if (role == 0) {
                    s_rz[0][unit].x = sigfast(acc0 + x0);
                    s_rz[1][unit].x = sigfast(acc1 + x1);
                } else if (role == 1) {
                    s_rz[0][unit].y = sigfast(acc0 + x0);
                    s_rz[1][unit].y = sigfast(acc1 + x1);
                }
                asm volatile("bar.sync %0, 96;" :: "r"(blk + 1) : "memory");
                if (role == 2) {
                    float2 rz0 = s_rz[0][unit];
                    float2 rz1 = s_rz[1][unit];
                    float n0 = tanha(fmaf(rz0.x, acc0, x0));
                    float n1 = tanha(fmaf(rz1.x, acc1, x1));
                    h0 = fmaf(rz0.y, h0 - n0, n0);
                    h1 = fmaf(rz1.y, h1 - n1, n1);
                    hsm[cur ^ 1][0][hidx] = h0;
                    hsm[cur ^ 1][1][hidx] = h1;
                    yp[0] = h0;
                    yp[TT * HH] = h1;
                }
                __syncthreads();
                x0 = xn0; x1 = xn1;
                xo += GG;
                yp += HH;
                cur ^= 1;
            }
            if (tid == 0) {                     // self-reset for next replay
                stplain(fl + c, 0);
                stplain(fl + c + 32, 0);
            }
        }
        if (role == 2) {
            hT[(BB + b0) * HH + unit] = h0;
            hT[(BB + b0) * HH + HH + unit] = h1;
        }
    }
}

// ---------- Tail: out[b,t] = relu(y1[b,t,:]) . fc_w + fc_b  (memory-bound) ----------
__global__ void __launch_bounds__(256)
k_fc(const float* __restrict__ fc_w, const float* __restrict__ fc_b,
     float* __restrict__ out) {
    const int row = blockIdx.x * 8 + (threadIdx.x >> 5);   // row = b*TT + t
    const int lane = threadIdx.x & 31;
    float4 yv = ((const float4*)(g_y1 + (size_t)row * HH))[lane];
    float4 wv = ((const float4*)fc_w)[lane];
    float p = fmaxf(yv.x, 0.f) * wv.x + fmaxf(yv.y, 0.f) * wv.y
            + fmaxf(yv.z, 0.f) * wv.z + fmaxf(yv.w, 0.f) * wv.w;
    p += __shfl_xor_sync(0xffffffffu, p, 16);
    p += __shfl_xor_sync(0xffffffffu, p, 8);
    p += __shfl_xor_sync(0xffffffffu, p, 4);
    p += __shfl_xor_sync(0xffffffffu, p, 2);
    p += __shfl_xor_sync(0xffffffffu, p, 1);
    if (lane == 0) out[row] = p + fc_b[0];
}

extern "C" void kernel_launch(void* const* d_in, const int* in_sizes, int n_in,
                              void* d_out, int out_size) {
    const float* data   = (const float*)d_in[0];
    const float* hidden = (const float*)d_in[1];
    const float* w_ih0  = (const float*)d_in[2];
    const float* w_hh0  = (const float*)d_in[3];
    const float* b_ih0  = (const float*)d_in[4];
    const float* b_hh0  = (const float*)d_in[5];
    const float* w_ih1  = (const float*)d_in[6];
    const float* w_hh1  = (const float*)d_in[7];
    const float* b_ih1  = (const float*)d_in[8];
    const float* b_hh1  = (const float*)d_in[9];
    const float* fc_w   = (const float*)d_in[10];
    const float* fc_b   = (const float*)d_in[11];

    float* out = (float*)d_out;
    float* hT  = out + (size_t)BB * TT;   // [2,B,H] final hidden

    k_main<<<2 * NPAIR + NWORK, 384>>>(data, hidden, w_ih0, w_hh0, b_ih0, b_hh0,
                                       w_ih1, w_hh1, b_ih1, b_hh1, hT);
    k_fc<<<BB * TT / 8, 256>>>(fc_w, fc_b, out);
}